// round 1
// baseline (speedup 1.0000x reference)
#include <cuda_runtime.h>

// Problem constants
#define NB 2
#define NC 128
#define NS 16384        // T*H*W = 4*64*64
#define NN 1024         // patch tokens: 4*16*16
#define NP 16           // pixels per patch
#define NG 32           // heads == groupnorm groups
#define TBL 6727        // (2T-1)*(2h-1)*(2w-1) = 7*31*31
#define EPS 1e-5f

// Scratch (static device memory; no allocations)
__device__ float g_y[3][NB][NC][NN][NP];       // raw projections, patch layout (~50MB)
__device__ float g_part[3][NB][NG][256][2];    // per-sTile partial (sum, sumsq)
__device__ float g_cscale[3][NB][NC];          // GN folded: scale = gamma*rstd
__device__ float g_cshift[3][NB][NC];          // GN folded: shift = beta - mu*scale
__device__ float g_qp[NB][NG][4][NN];          // pooled normalized q (pre-scaled 1/sqrt(d))
__device__ float g_kp[NB][NG][4][NN];          // pooled normalized k

// ---------------------------------------------------------------------------
// K1: projections. Y[o,s] = sum_c W[o,c] * x[c,s], per (proj, b).
// Block: 64 o x 64 s tile, k in chunks of 32. Thread: 4x4 micro-tile.
// Writes raw y in patch layout and per-(group, sTile) partial stats.
// ---------------------------------------------------------------------------
__global__ void __launch_bounds__(256) proj_kernel(
    const float* __restrict__ x, const float* __restrict__ Wq,
    const float* __restrict__ Wk, const float* __restrict__ Wv) {
  const int sTile = blockIdx.x;          // 0..255
  const int oTile = blockIdx.y;          // 0..1
  const int proj = blockIdx.z >> 1;      // 0..2
  const int b = blockIdx.z & 1;
  const float* __restrict__ W = (proj == 0) ? Wq : ((proj == 1) ? Wk : Wv);

  __shared__ float Wsh[32][68];          // transposed: [k][o_local], stride keeps 16B align
  __shared__ float Xsh[32][64];          // [k][s_local]
  __shared__ float redS[16][17];
  __shared__ float redQ[16][17];

  const int tid = threadIdx.x;
  const int oq = tid >> 4;               // 0..15
  const int sq = tid & 15;               // 0..15
  const int sl0 = sq * 4;
  const int s0 = sTile * 64 + sl0;

  float acc[4][4];
#pragma unroll
  for (int i = 0; i < 4; i++)
#pragma unroll
    for (int j = 0; j < 4; j++) acc[i][j] = 0.f;

  const float* __restrict__ xb = x + (size_t)b * NC * NS;

  for (int kc = 0; kc < 128; kc += 32) {
    __syncthreads();
#pragma unroll
    for (int i = tid; i < 2048; i += 256) {
      int ol = i >> 5, kk = i & 31;
      Wsh[kk][ol] = W[(oTile * 64 + ol) * 128 + kc + kk];
    }
#pragma unroll
    for (int i = tid; i < 2048; i += 256) {
      int kk = i >> 6, ss = i & 63;
      Xsh[kk][ss] = xb[(size_t)(kc + kk) * NS + sTile * 64 + ss];
    }
    __syncthreads();
#pragma unroll 8
    for (int k = 0; k < 32; k++) {
      float4 a = *(const float4*)&Wsh[k][oq * 4];
      float4 xv = *(const float4*)&Xsh[k][sl0];
      acc[0][0] += a.x * xv.x; acc[0][1] += a.x * xv.y; acc[0][2] += a.x * xv.z; acc[0][3] += a.x * xv.w;
      acc[1][0] += a.y * xv.x; acc[1][1] += a.y * xv.y; acc[1][2] += a.y * xv.z; acc[1][3] += a.y * xv.w;
      acc[2][0] += a.z * xv.x; acc[2][1] += a.z * xv.y; acc[2][2] += a.z * xv.z; acc[2][3] += a.z * xv.w;
      acc[3][0] += a.w * xv.x; acc[3][1] += a.w * xv.y; acc[3][2] += a.w * xv.z; acc[3][3] += a.w * xv.w;
    }
  }

  // Partial group stats: each thread's 4 channels (o0..o0+3) lie in one group.
  float ls = 0.f, lq = 0.f;
#pragma unroll
  for (int i = 0; i < 4; i++)
#pragma unroll
    for (int j = 0; j < 4; j++) { float v = acc[i][j]; ls += v; lq += v * v; }
  redS[oq][sq] = ls;
  redQ[oq][sq] = lq;
  __syncthreads();
  if (tid < 16) {
    float s = 0.f, q = 0.f;
#pragma unroll
    for (int rme = 0; rme < 16; rme++) { s += redS[tid][rme]; q += redQ[tid][rme]; }
    g_part[proj][b][oTile * 16 + tid][sTile][0] = s;
    g_part[proj][b][oTile * 16 + tid][sTile][1] = q;
  }

  // Write y in patch layout [proj][b][o][n][p]
  const int t = s0 >> 12;
  const int yrow = (s0 >> 6) & 63;
  const int x0 = s0 & 63;
  const int hp = yrow >> 2, ph = yrow & 3, wp = x0 >> 2;
  const int n = (t << 8) + (hp << 4) + wp;
  const int p0 = ph << 2;
  const int o0 = oTile * 64 + oq * 4;
#pragma unroll
  for (int oi = 0; oi < 4; oi++) {
    float* dst = &g_y[proj][b][o0 + oi][n][p0];
    *(float4*)dst = make_float4(acc[oi][0], acc[oi][1], acc[oi][2], acc[oi][3]);
  }
}

// ---------------------------------------------------------------------------
// K2: finalize GN stats -> per-channel (scale, shift). 192 blocks, 256 thr.
// ---------------------------------------------------------------------------
__global__ void __launch_bounds__(256) stats_kernel(
    const float* __restrict__ gqg, const float* __restrict__ gqb,
    const float* __restrict__ gkg, const float* __restrict__ gkb,
    const float* __restrict__ gvg, const float* __restrict__ gvb) {
  const int gid = blockIdx.x;            // proj*64 + b*32 + g
  const int proj = gid >> 6;
  const int rem = gid & 63;
  const int b = rem >> 5;
  const int g = rem & 31;
  const int tid = threadIdx.x;

  __shared__ float sS[256];
  __shared__ float sQ[256];
  sS[tid] = g_part[proj][b][g][tid][0];
  sQ[tid] = g_part[proj][b][g][tid][1];
  __syncthreads();
  for (int st = 128; st > 0; st >>= 1) {
    if (tid < st) { sS[tid] += sS[tid + st]; sQ[tid] += sQ[tid + st]; }
    __syncthreads();
  }
  __shared__ float mu_s, rstd_s;
  if (tid == 0) {
    float mu = sS[0] * (1.f / 65536.f);
    float var = sQ[0] * (1.f / 65536.f) - mu * mu;
    mu_s = mu;
    rstd_s = rsqrtf(var + EPS);
  }
  __syncthreads();
  if (tid < 4) {
    int o = g * 4 + tid;
    const float* gam = (proj == 0) ? gqg : ((proj == 1) ? gkg : gvg);
    const float* bet = (proj == 0) ? gqb : ((proj == 1) ? gkb : gvb);
    float sc = gam[o] * rstd_s;
    g_cscale[proj][b][o] = sc;
    g_cshift[proj][b][o] = bet[o] - mu_s * sc;
  }
}

// ---------------------------------------------------------------------------
// K3: pool q/k over the 16 pixels, apply GN affine, pre-scale q by 1/sqrt(d).
// ---------------------------------------------------------------------------
__global__ void __launch_bounds__(256) pool_kernel() {
  const int idx = blockIdx.x * 256 + threadIdx.x;  // 524288 total
  const int n = idx & 1023;
  const int d = (idx >> 10) & 3;
  const int g = (idx >> 12) & 31;
  const int b = (idx >> 17) & 1;
  const int which = idx >> 18;                     // 0 = q, 1 = k
  const int o = g * 4 + d;
  const float4* src = (const float4*)&g_y[which][b][o][n][0];
  float sum = 0.f;
#pragma unroll
  for (int u = 0; u < 4; u++) { float4 v = src[u]; sum += v.x + v.y + v.z + v.w; }
  float val = g_cscale[which][b][o] * (sum * (1.f / 16.f)) + g_cshift[which][b][o];
  if (which == 0)
    g_qp[b][g][d][n] = val * 0.5f;   // 1/sqrt(d)=0.5 folded
  else
    g_kp[b][g][d][n] = val;
}

// ---------------------------------------------------------------------------
// K4: fused attention. Block = (b, g, 64-row tile). Online softmax over
// m-tiles of 64. vp tile staged in SMEM with GN affine folded. Thread:
// 2 rows x 8 (d,p) outputs.
// ---------------------------------------------------------------------------
__global__ void __launch_bounds__(256) attn_kernel(
    const float* __restrict__ rel_table, const int* __restrict__ rel_index,
    float* __restrict__ out) {
  const int bg = blockIdx.y;
  const int b = bg >> 5;
  const int g = bg & 31;
  const int nTile = blockIdx.x;
  const int tid = threadIdx.x;
  const int r = tid >> 3;          // 0..31 (row group)
  const int dq = tid & 7;          // 0..7
  const int dpBase = dq * 8;       // 8 consecutive (d,p) outputs
  const int d = dpBase >> 4;       // 0..3
  const int pBase = dpBase & 15;   // 0 or 8
  const int n0 = nTile * 64 + r;
  const int n1 = n0 + 32;

  __shared__ float kpsh[4][64];
  __shared__ float vpsh[64][64];
  __shared__ float wsh[64][65];

  float qa[4], qb[4];
#pragma unroll
  for (int dd = 0; dd < 4; dd++) {
    qa[dd] = g_qp[b][g][dd][n0];
    qb[dd] = g_qp[b][g][dd][n1];
  }
  const float* __restrict__ tbl = rel_table + g * TBL;
  const int* __restrict__ ri0 = rel_index + (size_t)n0 * NN;
  const int* __restrict__ ri1 = rel_index + (size_t)n1 * NN;

  // vp loader assignment: each thread copies 16 floats (one (m, d) stripe)
  const int mloc = tid >> 2;
  const int dl = tid & 3;
  const int ol = g * 4 + dl;
  const float vsc = g_cscale[2][b][ol];
  const float vsh = g_cshift[2][b][ol];

  float acc0[8], acc1[8];
#pragma unroll
  for (int u = 0; u < 8; u++) { acc0[u] = 0.f; acc1[u] = 0.f; }
  float rm0 = -1e30f, rm1 = -1e30f, rs0 = 0.f, rs1 = 0.f;

  for (int mt = 0; mt < 16; mt++) {
    __syncthreads();
    // kp tile
    {
      int dd = tid >> 6, j = tid & 63;
      kpsh[dd][j] = g_kp[b][g][dd][mt * 64 + j];
    }
    // vp tile with GN affine folded
    {
      const float4* src = (const float4*)&g_y[2][b][ol][mt * 64 + mloc][0];
      float4* dst = (float4*)&vpsh[mloc][dl * 16];
#pragma unroll
      for (int u = 0; u < 4; u++) {
        float4 v = src[u];
        v.x = v.x * vsc + vsh; v.y = v.y * vsc + vsh;
        v.z = v.z * vsc + vsh; v.w = v.w * vsc + vsh;
        dst[u] = v;
      }
    }
    __syncthreads();

    // logits: thread handles 8 m values (stride 8) for each of its 2 rows
    float l0[8], l1[8];
#pragma unroll
    for (int j = 0; j < 8; j++) {
      int ml = dq + j * 8;
      int mg = mt * 64 + ml;
      float d0 = qa[0] * kpsh[0][ml] + qa[1] * kpsh[1][ml] +
                 qa[2] * kpsh[2][ml] + qa[3] * kpsh[3][ml];
      float d1 = qb[0] * kpsh[0][ml] + qb[1] * kpsh[1][ml] +
                 qb[2] * kpsh[2][ml] + qb[3] * kpsh[3][ml];
      l0[j] = d0 + tbl[ri0[mg]];
      l1[j] = d1 + tbl[ri1[mg]];
    }
    // tile max per row via shfl across the row's 8 lanes
    float tm0 = l0[0], tm1 = l1[0];
#pragma unroll
    for (int j = 1; j < 8; j++) { tm0 = fmaxf(tm0, l0[j]); tm1 = fmaxf(tm1, l1[j]); }
#pragma unroll
    for (int k = 1; k < 8; k <<= 1) {
      tm0 = fmaxf(tm0, __shfl_xor_sync(0xffffffffu, tm0, k, 8));
      tm1 = fmaxf(tm1, __shfl_xor_sync(0xffffffffu, tm1, k, 8));
    }
    float nm0 = fmaxf(rm0, tm0), nm1 = fmaxf(rm1, tm1);
    float al0 = __expf(rm0 - nm0), al1 = __expf(rm1 - nm1);
    rs0 *= al0; rs1 *= al1;
#pragma unroll
    for (int u = 0; u < 8; u++) { acc0[u] *= al0; acc1[u] *= al1; }
    rm0 = nm0; rm1 = nm1;

    float ts0 = 0.f, ts1 = 0.f;
#pragma unroll
    for (int j = 0; j < 8; j++) {
      float p0 = __expf(l0[j] - nm0);
      float p1 = __expf(l1[j] - nm1);
      ts0 += p0; ts1 += p1;
      wsh[r][dq + j * 8] = p0;
      wsh[r + 32][dq + j * 8] = p1;
    }
#pragma unroll
    for (int k = 1; k < 8; k <<= 1) {
      ts0 += __shfl_xor_sync(0xffffffffu, ts0, k, 8);
      ts1 += __shfl_xor_sync(0xffffffffu, ts1, k, 8);
    }
    rs0 += ts0; rs1 += ts1;
    __syncthreads();

    // AV accumulation
#pragma unroll 8
    for (int m = 0; m < 64; m++) {
      float w0 = wsh[r][m];
      float w1 = wsh[r + 32][m];
      float4 va = *(const float4*)&vpsh[m][dpBase];
      float4 vb = *(const float4*)&vpsh[m][dpBase + 4];
      acc0[0] += w0 * va.x; acc0[1] += w0 * va.y; acc0[2] += w0 * va.z; acc0[3] += w0 * va.w;
      acc0[4] += w0 * vb.x; acc0[5] += w0 * vb.y; acc0[6] += w0 * vb.z; acc0[7] += w0 * vb.w;
      acc1[0] += w1 * va.x; acc1[1] += w1 * va.y; acc1[2] += w1 * va.z; acc1[3] += w1 * va.w;
      acc1[4] += w1 * vb.x; acc1[5] += w1 * vb.y; acc1[6] += w1 * vb.z; acc1[7] += w1 * vb.w;
    }
  }

  // Epilogue: normalize and un-patch to (B,C,T,H,W)
  const float inv0 = 1.f / rs0;
  const float inv1 = 1.f / rs1;
  const int o = g * 4 + d;
  const int phBase = pBase >> 2;
  {
    int t = n0 >> 8, hp = (n0 >> 4) & 15, wp = n0 & 15;
    float* base = out + ((size_t)(b * NC + o)) * NS + t * 4096 + wp * 4;
#pragma unroll
    for (int e = 0; e < 2; e++) {
      int ph = phBase + e;
      *(float4*)(base + (hp * 4 + ph) * 64) =
          make_float4(acc0[e * 4 + 0] * inv0, acc0[e * 4 + 1] * inv0,
                      acc0[e * 4 + 2] * inv0, acc0[e * 4 + 3] * inv0);
    }
  }
  {
    int t = n1 >> 8, hp = (n1 >> 4) & 15, wp = n1 & 15;
    float* base = out + ((size_t)(b * NC + o)) * NS + t * 4096 + wp * 4;
#pragma unroll
    for (int e = 0; e < 2; e++) {
      int ph = phBase + e;
      *(float4*)(base + (hp * 4 + ph) * 64) =
          make_float4(acc1[e * 4 + 0] * inv1, acc1[e * 4 + 1] * inv1,
                      acc1[e * 4 + 2] * inv1, acc1[e * 4 + 3] * inv1);
    }
  }
}

// ---------------------------------------------------------------------------
extern "C" void kernel_launch(void* const* d_in, const int* in_sizes, int n_in,
                              void* d_out, int out_size) {
  (void)in_sizes; (void)n_in; (void)out_size;
  const float* x   = (const float*)d_in[0];
  const float* Wq  = (const float*)d_in[1];
  const float* Wk  = (const float*)d_in[2];
  const float* Wv  = (const float*)d_in[3];
  const float* gqg = (const float*)d_in[4];
  const float* gqb = (const float*)d_in[5];
  const float* gkg = (const float*)d_in[6];
  const float* gkb = (const float*)d_in[7];
  const float* gvg = (const float*)d_in[8];
  const float* gvb = (const float*)d_in[9];
  const float* rel_table = (const float*)d_in[10];
  const int*   rel_index = (const int*)d_in[11];
  float* out = (float*)d_out;

  proj_kernel<<<dim3(256, 2, 6), 256>>>(x, Wq, Wk, Wv);
  stats_kernel<<<192, 256>>>(gqg, gqb, gkg, gkb, gvg, gvb);
  pool_kernel<<<2048, 256>>>();
  attn_kernel<<<dim3(16, 64), 256>>>(rel_table, rel_index, out);
}

// round 2
// speedup vs baseline: 1.6830x; 1.6830x over previous
#include <cuda_runtime.h>

// Problem constants
#define NB 2
#define NC 128
#define NS 16384        // T*H*W = 4*64*64
#define NN 1024         // patch tokens: 4*16*16
#define NP 16           // pixels per patch
#define NG 32           // heads == groupnorm groups
#define TBL 6727        // (2T-1)*(2h-1)*(2w-1) = 7*31*31
#define EPS 1e-5f

typedef unsigned long long ull;

// Scratch (static device memory; no allocations)
__device__ float g_y[3][NB][NC][NN][NP];       // raw projections, patch layout (~50MB)
__device__ float g_part[3][NB][NG][256][2];    // per-sTile partial (sum, sumsq)
__device__ float g_cscale[3][NB][NC];          // GN folded: scale = gamma*rstd
__device__ float g_cshift[3][NB][NC];          // GN folded: shift = beta - mu*scale
__device__ float g_qp[NB][NG][4][NN];          // pooled normalized q (pre-scaled 1/sqrt(d))
__device__ float g_kp[NB][NG][4][NN];          // pooled normalized k

// Packed f32x2 FMA (SASS FFMA2: rt_SMSP=1 pair/2cyc -> 2x fp32 throughput)
static __device__ __forceinline__ ull fma2(ull a, ull b, ull c) {
  ull d;
  asm("fma.rn.f32x2 %0, %1, %2, %3;" : "=l"(d) : "l"(a), "l"(b), "l"(c));
  return d;
}
static __device__ __forceinline__ float2 ull2f2(ull u) {
  float2 f;
  f.x = __uint_as_float((unsigned)u);
  f.y = __uint_as_float((unsigned)(u >> 32));
  return f;
}

// ---------------------------------------------------------------------------
// K1: projections. Y[o,s] = sum_c W[o,c] * x[c,s], per (proj, b).
// ---------------------------------------------------------------------------
__global__ void __launch_bounds__(256) proj_kernel(
    const float* __restrict__ x, const float* __restrict__ Wq,
    const float* __restrict__ Wk, const float* __restrict__ Wv) {
  const int sTile = blockIdx.x;          // 0..255
  const int oTile = blockIdx.y;          // 0..1
  const int proj = blockIdx.z >> 1;      // 0..2
  const int b = blockIdx.z & 1;
  const float* __restrict__ W = (proj == 0) ? Wq : ((proj == 1) ? Wk : Wv);

  __shared__ float Wsh[32][68];
  __shared__ float Xsh[32][64];
  __shared__ float redS[16][17];
  __shared__ float redQ[16][17];

  const int tid = threadIdx.x;
  const int oq = tid >> 4;
  const int sq = tid & 15;
  const int sl0 = sq * 4;
  const int s0 = sTile * 64 + sl0;

  float acc[4][4];
#pragma unroll
  for (int i = 0; i < 4; i++)
#pragma unroll
    for (int j = 0; j < 4; j++) acc[i][j] = 0.f;

  const float* __restrict__ xb = x + (size_t)b * NC * NS;

  for (int kc = 0; kc < 128; kc += 32) {
    __syncthreads();
#pragma unroll
    for (int i = tid; i < 2048; i += 256) {
      int ol = i >> 5, kk = i & 31;
      Wsh[kk][ol] = W[(oTile * 64 + ol) * 128 + kc + kk];
    }
#pragma unroll
    for (int i = tid; i < 2048; i += 256) {
      int kk = i >> 6, ss = i & 63;
      Xsh[kk][ss] = xb[(size_t)(kc + kk) * NS + sTile * 64 + ss];
    }
    __syncthreads();
#pragma unroll 8
    for (int k = 0; k < 32; k++) {
      float4 a = *(const float4*)&Wsh[k][oq * 4];
      float4 xv = *(const float4*)&Xsh[k][sl0];
      acc[0][0] += a.x * xv.x; acc[0][1] += a.x * xv.y; acc[0][2] += a.x * xv.z; acc[0][3] += a.x * xv.w;
      acc[1][0] += a.y * xv.x; acc[1][1] += a.y * xv.y; acc[1][2] += a.y * xv.z; acc[1][3] += a.y * xv.w;
      acc[2][0] += a.z * xv.x; acc[2][1] += a.z * xv.y; acc[2][2] += a.z * xv.z; acc[2][3] += a.z * xv.w;
      acc[3][0] += a.w * xv.x; acc[3][1] += a.w * xv.y; acc[3][2] += a.w * xv.z; acc[3][3] += a.w * xv.w;
    }
  }

  float ls = 0.f, lq = 0.f;
#pragma unroll
  for (int i = 0; i < 4; i++)
#pragma unroll
    for (int j = 0; j < 4; j++) { float v = acc[i][j]; ls += v; lq += v * v; }
  redS[oq][sq] = ls;
  redQ[oq][sq] = lq;
  __syncthreads();
  if (tid < 16) {
    float s = 0.f, q = 0.f;
#pragma unroll
    for (int rme = 0; rme < 16; rme++) { s += redS[tid][rme]; q += redQ[tid][rme]; }
    g_part[proj][b][oTile * 16 + tid][sTile][0] = s;
    g_part[proj][b][oTile * 16 + tid][sTile][1] = q;
  }

  const int t = s0 >> 12;
  const int yrow = (s0 >> 6) & 63;
  const int x0 = s0 & 63;
  const int hp = yrow >> 2, ph = yrow & 3, wp = x0 >> 2;
  const int n = (t << 8) + (hp << 4) + wp;
  const int p0 = ph << 2;
  const int o0 = oTile * 64 + oq * 4;
#pragma unroll
  for (int oi = 0; oi < 4; oi++) {
    float* dst = &g_y[proj][b][o0 + oi][n][p0];
    *(float4*)dst = make_float4(acc[oi][0], acc[oi][1], acc[oi][2], acc[oi][3]);
  }
}

// ---------------------------------------------------------------------------
// K2: finalize GN stats -> per-channel (scale, shift).
// ---------------------------------------------------------------------------
__global__ void __launch_bounds__(256) stats_kernel(
    const float* __restrict__ gqg, const float* __restrict__ gqb,
    const float* __restrict__ gkg, const float* __restrict__ gkb,
    const float* __restrict__ gvg, const float* __restrict__ gvb) {
  const int gid = blockIdx.x;
  const int proj = gid >> 6;
  const int rem = gid & 63;
  const int b = rem >> 5;
  const int g = rem & 31;
  const int tid = threadIdx.x;

  __shared__ float sS[256];
  __shared__ float sQ[256];
  sS[tid] = g_part[proj][b][g][tid][0];
  sQ[tid] = g_part[proj][b][g][tid][1];
  __syncthreads();
  for (int st = 128; st > 0; st >>= 1) {
    if (tid < st) { sS[tid] += sS[tid + st]; sQ[tid] += sQ[tid + st]; }
    __syncthreads();
  }
  __shared__ float mu_s, rstd_s;
  if (tid == 0) {
    float mu = sS[0] * (1.f / 65536.f);
    float var = sQ[0] * (1.f / 65536.f) - mu * mu;
    mu_s = mu;
    rstd_s = rsqrtf(var + EPS);
  }
  __syncthreads();
  if (tid < 4) {
    int o = g * 4 + tid;
    const float* gam = (proj == 0) ? gqg : ((proj == 1) ? gkg : gvg);
    const float* bet = (proj == 0) ? gqb : ((proj == 1) ? gkb : gvb);
    float sc = gam[o] * rstd_s;
    g_cscale[proj][b][o] = sc;
    g_cshift[proj][b][o] = bet[o] - mu_s * sc;
  }
}

// ---------------------------------------------------------------------------
// K3: pool q/k, apply GN affine, fold 1/sqrt(d) into q.
// ---------------------------------------------------------------------------
__global__ void __launch_bounds__(256) pool_kernel() {
  const int idx = blockIdx.x * 256 + threadIdx.x;
  const int n = idx & 1023;
  const int d = (idx >> 10) & 3;
  const int g = (idx >> 12) & 31;
  const int b = (idx >> 17) & 1;
  const int which = idx >> 18;
  const int o = g * 4 + d;
  const float4* src = (const float4*)&g_y[which][b][o][n][0];
  float sum = 0.f;
#pragma unroll
  for (int u = 0; u < 4; u++) { float4 v = src[u]; sum += v.x + v.y + v.z + v.w; }
  float val = g_cscale[which][b][o] * (sum * (1.f / 16.f)) + g_cshift[which][b][o];
  if (which == 0)
    g_qp[b][g][d][n] = val * 0.5f;
  else
    g_kp[b][g][d][n] = val;
}

// ---------------------------------------------------------------------------
// K4: fused attention. Block = (b,g, 128-row tile). m-tiles of 32.
// Phase A: warp w computes rows w*16..w*16+15, lane = m within tile.
//          p = exp(q.k + bias) stored duplicated {p,p} for packed AV.
//          Bias index computed arithmetically (separable); table LDG coalesced.
// Phase B: thread = 8 rows (interleaved by 2) x 4 cols, fma.rn.f32x2.
// No online-softmax rescale: logits bounded, plain exp + final 1/sum.
// ---------------------------------------------------------------------------
__global__ void __launch_bounds__(256, 2) attn_kernel(
    const float* __restrict__ rel_table, float* __restrict__ out) {
  const int bg = blockIdx.y;
  const int b = bg >> 5;
  const int g = bg & 31;
  const int nbase = blockIdx.x * 128;
  const int tid = threadIdx.x;
  const int wid = tid >> 5;
  const int lane = tid & 31;

  __shared__ float wsh[128][68];   // duplicated probs: [row][2*m_local(+pair)]
  __shared__ float vpsh[32][68];   // [m_local][dp]
  __shared__ float qsh[128][4];
  __shared__ int   crsh[128];
  __shared__ float invsh[128];

  // One-time fills
  if (tid < 128) {
    int n = nbase + tid;
    float4 qv;
    qv.x = g_qp[b][g][0][n];
    qv.y = g_qp[b][g][1][n];
    qv.z = g_qp[b][g][2][n];
    qv.w = g_qp[b][g][3][n];
    *(float4*)qsh[tid] = qv;
    int t = n >> 8, y = (n >> 4) & 15, xx = n & 15;
    crsh[tid] = ((t + 3) * 31 + y + 15) * 31 + xx + 15;
  }

  // vp-fill constants: thread loads 8 consecutive dp floats of one m row
  const int v_ml = tid >> 3;               // 0..31
  const int v_dp0 = (tid & 7) * 8;         // 0..56
  const int v_d = v_dp0 >> 4;
  const int v_p0 = v_dp0 & 15;             // 0 or 8
  const int v_o = g * 4 + v_d;
  const float vsc = g_cscale[2][b][v_o];
  const float vshf = g_cshift[2][b][v_o];
  const float* v_src = &g_y[2][b][v_o][0][v_p0];

  // Phase-B constants
  const int rh = lane >> 4;                // 0/1
  const int c4 = lane & 15;
  const int c0 = c4 * 4;
  const int rbase = wid * 16 + rh;         // rows rbase + 2i

  const float* __restrict__ tb = rel_table + g * TBL;
  const float* kp0 = &g_kp[b][g][0][0];

  ull acc0[8], acc1[8];
#pragma unroll
  for (int i = 0; i < 8; i++) { acc0[i] = 0ull; acc1[i] = 0ull; }
  float rs[16];
#pragma unroll
  for (int i = 0; i < 16; i++) rs[i] = 0.f;

  for (int mt = 0; mt < 32; mt++) {
    __syncthreads();   // prev phase B done with wsh/vpsh; (mt=0: qsh/crsh ready)

    // vp tile fill (GN affine folded)
    {
      const float4* s = (const float4*)(v_src + (size_t)(mt * 32 + v_ml) * 16);
      float4 a = s[0], c = s[1];
      a.x = a.x * vsc + vshf; a.y = a.y * vsc + vshf; a.z = a.z * vsc + vshf; a.w = a.w * vsc + vshf;
      c.x = c.x * vsc + vshf; c.y = c.y * vsc + vshf; c.z = c.z * vsc + vshf; c.w = c.w * vsc + vshf;
      *(float4*)&vpsh[v_ml][v_dp0] = a;
      *(float4*)&vpsh[v_ml][v_dp0 + 4] = c;
    }

    // Phase A: lane = m, loop rows
    {
      const int m = mt * 32 + lane;
      const float k0 = kp0[m];
      const float k1 = kp0[NN + m];
      const float k2 = kp0[2 * NN + m];
      const float k3 = kp0[3 * NN + m];
      const int tm = m >> 8, ym = (m >> 4) & 15, xm = m & 15;
      const int cm = (tm * 31 + ym) * 31 + xm;
#pragma unroll
      for (int i = 0; i < 16; i++) {
        int r = wid * 16 + i;
        float4 q = *(const float4*)qsh[r];
        float lg = q.x * k0 + q.y * k1 + q.z * k2 + q.w * k3;
        float bias = __ldg(tb + (crsh[r] - cm));
        float p = __expf(lg + bias);
        rs[i] += p;
        *(float2*)&wsh[r][lane * 2] = make_float2(p, p);
      }
    }
    __syncthreads();

    // Phase B: AV with packed f32x2 FMA
#pragma unroll
    for (int mc = 0; mc < 8; mc++) {
      const int m0 = mc * 4;
      ull vA[4], vB[4];
#pragma unroll
      for (int j = 0; j < 4; j++) {
        ulonglong2 vv = *(const ulonglong2*)&vpsh[m0 + j][c0];
        vA[j] = vv.x; vB[j] = vv.y;
      }
#pragma unroll
      for (int i = 0; i < 8; i++) {
        int r = rbase + 2 * i;
        ulonglong2 w01 = *(const ulonglong2*)&wsh[r][m0 * 2];
        ulonglong2 w23 = *(const ulonglong2*)&wsh[r][m0 * 2 + 4];
        acc0[i] = fma2(w01.x, vA[0], acc0[i]); acc1[i] = fma2(w01.x, vB[0], acc1[i]);
        acc0[i] = fma2(w01.y, vA[1], acc0[i]); acc1[i] = fma2(w01.y, vB[1], acc1[i]);
        acc0[i] = fma2(w23.x, vA[2], acc0[i]); acc1[i] = fma2(w23.x, vB[2], acc1[i]);
        acc0[i] = fma2(w23.y, vA[3], acc0[i]); acc1[i] = fma2(w23.y, vB[3], acc1[i]);
      }
    }
  }

  // Row-sum reduction (lane-partial over m) -> invsh
#pragma unroll
  for (int i = 0; i < 16; i++) {
    float s = rs[i];
    s += __shfl_xor_sync(0xffffffffu, s, 16);
    s += __shfl_xor_sync(0xffffffffu, s, 8);
    s += __shfl_xor_sync(0xffffffffu, s, 4);
    s += __shfl_xor_sync(0xffffffffu, s, 2);
    s += __shfl_xor_sync(0xffffffffu, s, 1);
    if (lane == 0) invsh[wid * 16 + i] = 1.f / s;
  }
  __syncthreads();

  // Epilogue: normalize + un-patch store
  const int dB = c4 >> 2;
  const int phB = c4 & 3;
  float* obase = out + ((size_t)(b * NC + g * 4 + dB)) * NS;
#pragma unroll
  for (int i = 0; i < 8; i++) {
    int r = rbase + 2 * i;
    int n = nbase + r;
    float iv = invsh[r];
    float2 a = ull2f2(acc0[i]);
    float2 c = ull2f2(acc1[i]);
    int t = n >> 8, hp = (n >> 4) & 15, wp = n & 15;
    *(float4*)(obase + t * 4096 + (hp * 4 + phB) * 64 + wp * 4) =
        make_float4(a.x * iv, a.y * iv, c.x * iv, c.y * iv);
  }
}

// ---------------------------------------------------------------------------
extern "C" void kernel_launch(void* const* d_in, const int* in_sizes, int n_in,
                              void* d_out, int out_size) {
  (void)in_sizes; (void)n_in; (void)out_size;
  const float* x   = (const float*)d_in[0];
  const float* Wq  = (const float*)d_in[1];
  const float* Wk  = (const float*)d_in[2];
  const float* Wv  = (const float*)d_in[3];
  const float* gqg = (const float*)d_in[4];
  const float* gqb = (const float*)d_in[5];
  const float* gkg = (const float*)d_in[6];
  const float* gkb = (const float*)d_in[7];
  const float* gvg = (const float*)d_in[8];
  const float* gvb = (const float*)d_in[9];
  const float* rel_table = (const float*)d_in[10];
  float* out = (float*)d_out;

  proj_kernel<<<dim3(256, 2, 6), 256>>>(x, Wq, Wk, Wv);
  stats_kernel<<<192, 256>>>(gqg, gqb, gkg, gkb, gvg, gvb);
  pool_kernel<<<2048, 256>>>();
  attn_kernel<<<dim3(8, 64), 256>>>(rel_table, out);
}